// round 6
// baseline (speedup 1.0000x reference)
#include <cuda_runtime.h>
#include <cuda_bf16.h>

// Dilate (zero-insertion upsample) with stride (2,2):
//   in : (16, 64, 256, 256) fp32
//   out: (16, 64, 512, 512) fp32, out[b,c,2i,2j] = in[b,c,i,j], rest 0.
//
// Branch-free: one even/odd output-row PAIR (4KB contiguous) per warp.
// Lane handles float4 offsets lane + {0,32,64,96} in the even row (data
// interleaved with zeros) and lane + {128,160,192,224} in the odd row
// (all zeros). Every store is a warp-contiguous 512B wavefront; the 4KB
// written per warp is one contiguous block. 4 front-batched 256B-coalesced
// loads cover the full 1KB input row.
// Traffic: 268MB read + 1.074GB write = the exact floor.

#ifndef DIL_THREADS
#define DIL_THREADS 256
#endif

__global__ void __launch_bounds__(DIL_THREADS)
Dilate_35708358099161_kernel(const float2* __restrict__ in2,
                             float4* __restrict__ out4)
{
    unsigned int tid  = blockIdx.x * DIL_THREADS + threadIdx.x;
    unsigned int w    = tid >> 5;        // warp id == global input row
    unsigned int lane = tid & 31u;

    unsigned int hin = w & 255u;         // input row within image
    unsigned int bc  = w >> 8;           // image index, 0..1023

    // input float2 base for this lane
    unsigned int base = (bc << 15) + (hin << 7) + lane;

    // four independent 256B-coalesced loads (full 1KB input row per warp)
    float2 a = __ldcs(&in2[base]);
    float2 b = __ldcs(&in2[base + 32]);
    float2 c = __ldcs(&in2[base + 64]);
    float2 d = __ldcs(&in2[base + 96]);

    // even output row base in float4 units: (bc*512 + 2*hin)*128 + lane
    unsigned int v = (bc << 16) + (hin << 8) + lane;

    const float4 z = make_float4(0.f, 0.f, 0.f, 0.f);

    // even row: data interleaved with zeros (4 x 512B contiguous wavefronts)
    __stcs(&out4[v],       make_float4(a.x, 0.f, a.y, 0.f));
    __stcs(&out4[v + 32],  make_float4(b.x, 0.f, b.y, 0.f));
    __stcs(&out4[v + 64],  make_float4(c.x, 0.f, c.y, 0.f));
    __stcs(&out4[v + 96],  make_float4(d.x, 0.f, d.y, 0.f));
    // odd row directly below: all zeros (next 2KB, still contiguous)
    __stcs(&out4[v + 128], z);
    __stcs(&out4[v + 160], z);
    __stcs(&out4[v + 192], z);
    __stcs(&out4[v + 224], z);
}

extern "C" void kernel_launch(void* const* d_in, const int* in_sizes, int n_in,
                              void* d_out, int out_size)
{
    const float2* in2 = (const float2*)d_in[0];
    float4* out4 = (float4*)d_out;

    // one warp per input row: 16*64*256 = 262,144 warps -> 8,388,608 threads
    const unsigned int nthreads = (unsigned int)(out_size / 32);
    const unsigned int blocks = nthreads / DIL_THREADS;  // exact: 32,768

    Dilate_35708358099161_kernel<<<blocks, DIL_THREADS>>>(in2, out4);
}